// round 11
// baseline (speedup 1.0000x reference)
#include <cuda_runtime.h>
#include <cstdint>
#include <cstddef>

#define NN 100000
#define EE 1600000
#define TT (EE + NN)

// ---------------- scratch (static device globals; no allocation) ----------------
__device__ float g_h[(size_t)NN * 96];      // h (layer1), then h (layer2)
__device__ float g_out[(size_t)NN * 96];    // aggregation output per layer
__device__ float g_small[(size_t)NN * 32];  // h2in, then t (pre-lin1)
__device__ float g_es[NN];
__device__ float g_ed[NN];
__device__ int   g_deg[NN];
__device__ int   g_rowptr[NN + 1];
__device__ int   g_cursor[NN];
__device__ int   g_csr[TT];
__device__ int   g_bsum[1024];
__device__ int   g_is64;

// ---------------- f32x2 / cp.async helpers ----------------
__device__ __forceinline__ unsigned long long pack_dup(float a) {
    unsigned long long r;
    unsigned ai = __float_as_uint(a);
    asm("mov.b64 %0, {%1, %1};" : "=l"(r) : "r"(ai));
    return r;
}
__device__ __forceinline__ void fma2(unsigned long long& d, unsigned long long a,
                                     unsigned long long b) {
    asm("fma.rn.f32x2 %0, %1, %2, %0;" : "+l"(d) : "l"(a), "l"(b));
}
__device__ __forceinline__ void cp16(void* smem_dst, const void* gsrc, int valid_bytes) {
    unsigned sm = (unsigned)__cvta_generic_to_shared(smem_dst);
    asm volatile("cp.async.cg.shared.global [%0], [%1], 16, %2;"
                 :: "r"(sm), "l"(gsrc), "r"(valid_bytes));
}
__device__ __forceinline__ void cp_commit() {
    asm volatile("cp.async.commit_group;" ::: "memory");
}
__device__ __forceinline__ void cp_wait1() {
    asm volatile("cp.async.wait_group 1;" ::: "memory");
}
__device__ __forceinline__ void cp_wait0() {
    asm volatile("cp.async.wait_group 0;" ::: "memory");
}

// ---------------- edge-index dtype probe ----------------
__global__ void k_probe(const int* __restrict__ ei32) {
    if (threadIdx.x == 0 && blockIdx.x == 0) {
        int acc = 0;
        #pragma unroll 8
        for (int i = 1; i < 512; i += 2) acc |= ei32[i];
        g_is64 = (acc == 0) ? 1 : 0;
    }
}

__device__ __forceinline__ int load_idx(const void* ei, size_t i, int is64, int N) {
    int v = is64 ? (int)((const long long*)ei)[i] : ((const int*)ei)[i];
    v = v < 0 ? 0 : v;
    return v >= N ? N - 1 : v;
}

// ---------------- CSR construction ----------------
__global__ void k_init_deg(int N) {
    int i = blockIdx.x * blockDim.x + threadIdx.x;
    if (i < N) g_deg[i] = 1;  // self-loop
}

__global__ void k_count(const void* __restrict__ ei, int E, int N) {
    int i = blockIdx.x * blockDim.x + threadIdx.x;
    if (i < E) {
        int d = load_idx(ei, (size_t)E + i, g_is64, N);
        atomicAdd(&g_deg[d], 1);
    }
}

__global__ void k_scan_blocks(int N) {
    __shared__ int ws[32];
    int i = blockIdx.x * 1024 + threadIdx.x;
    int v = (i < N) ? g_deg[i] : 0;
    int x = v;
    int lane = threadIdx.x & 31, wid = threadIdx.x >> 5;
    #pragma unroll
    for (int o = 1; o < 32; o <<= 1) {
        int y = __shfl_up_sync(0xffffffffu, x, o);
        if (lane >= o) x += y;
    }
    if (lane == 31) ws[wid] = x;
    __syncthreads();
    if (wid == 0) {
        int w = ws[lane];
        #pragma unroll
        for (int o = 1; o < 32; o <<= 1) {
            int y = __shfl_up_sync(0xffffffffu, w, o);
            if (lane >= o) w += y;
        }
        ws[lane] = w;
    }
    __syncthreads();
    int excl = x - v + (wid ? ws[wid - 1] : 0);
    if (i < N) g_rowptr[i] = excl;
    if (threadIdx.x == 1023) g_bsum[blockIdx.x] = ws[31];
}

__global__ void k_scan_sums(int G, int N) {
    __shared__ int ws[32];
    int tid = threadIdx.x;
    int v = (tid < G) ? g_bsum[tid] : 0;
    int x = v;
    int lane = tid & 31, wid = tid >> 5;
    #pragma unroll
    for (int o = 1; o < 32; o <<= 1) {
        int y = __shfl_up_sync(0xffffffffu, x, o);
        if (lane >= o) x += y;
    }
    if (lane == 31) ws[wid] = x;
    __syncthreads();
    if (wid == 0) {
        int w = ws[lane];
        #pragma unroll
        for (int o = 1; o < 32; o <<= 1) {
            int y = __shfl_up_sync(0xffffffffu, w, o);
            if (lane >= o) w += y;
        }
        ws[lane] = w;
    }
    __syncthreads();
    int excl = x - v + (wid ? ws[wid - 1] : 0);
    if (tid < G) g_bsum[tid] = excl;
    if (tid == 1023) g_rowptr[N] = ws[31];
}

__global__ void k_scan_add(int N) {
    int i = blockIdx.x * blockDim.x + threadIdx.x;
    if (i < N) {
        int v = g_rowptr[i] + g_bsum[i >> 10];
        g_rowptr[i] = v;
        g_cursor[i] = v;
    }
}

__global__ void k_fill(const void* __restrict__ ei, int E, int N) {
    int i = blockIdx.x * blockDim.x + threadIdx.x;
    int tot = E + N;
    if (i >= tot) return;
    int s, d;
    if (i < E) {
        int is64 = g_is64;
        s = load_idx(ei, i, is64, N);
        d = load_idx(ei, (size_t)E + i, is64, N);
    } else {
        s = i - E;
        d = s;
    }
    int pos = atomicAdd(&g_cursor[d], 1);
    if (pos < TT) g_csr[pos] = s;
}

// ---------------- GEMM: C[N,96] = A[N,K] @ W[K,96], f32x2, cp.async double buffer ----
// block: 128 rows x 96 cols, 384 threads, thread tile 4 rows x 8 cols.
// KC=16 chunks, 2 smem buffers (33 KB static), cp.async overlaps stage(c+1) with compute(c).
template <int K>
__global__ __launch_bounds__(384, 2)
void k_gemm96(const float* __restrict__ A, const float* __restrict__ W,
              float* __restrict__ C, int N) {
    constexpr int KC = 16;
    constexpr int NCH = K / KC;
    __shared__ float As[2][128][KC + 4];   // 80B row stride (16B-aligned)
    __shared__ float Ws[2][KC][96];
    int tid = threadIdx.x;
    int row0 = blockIdx.x * 128;
    int qp = tid % 12;  // cols qp*8 .. qp*8+7
    int rg = tid / 12;  // rows rg*4 .. rg*4+3

    auto stage = [&](int c, int buf) {
        for (int i = tid; i < KC * 24; i += 384) {
            int k = i / 24, q = i % 24;
            cp16(&Ws[buf][k][q * 4], W + (size_t)(c * KC + k) * 96 + q * 4, 16);
        }
        for (int i = tid; i < 128 * (KC / 4); i += 384) {
            int r = i / (KC / 4), kq = i % (KC / 4);
            bool ok = (row0 + r) < N;
            const float* src = A + (ok ? ((size_t)(row0 + r) * K + c * KC + kq * 4) : 0);
            cp16(&As[buf][r][kq * 4], src, ok ? 16 : 0);
        }
    };

    unsigned long long acc[4][4];
    #pragma unroll
    for (int i = 0; i < 4; ++i)
        #pragma unroll
        for (int j = 0; j < 4; ++j) acc[i][j] = 0ull;

    stage(0, 0);
    cp_commit();

    #pragma unroll
    for (int c = 0; c < NCH; ++c) {
        if (c + 1 < NCH) {
            stage(c + 1, (c + 1) & 1);
            cp_commit();
            cp_wait1();   // chunk c's group has landed
        } else {
            cp_wait0();
        }
        __syncthreads();

        int buf = c & 1;
        #pragma unroll
        for (int k = 0; k < KC; k += 2) {
            float2 a01[4];
            #pragma unroll
            for (int i = 0; i < 4; ++i)
                a01[i] = *reinterpret_cast<const float2*>(&As[buf][rg * 4 + i][k]);
            #pragma unroll
            for (int kk = 0; kk < 2; ++kk) {
                ulonglong2 w01 =
                    *reinterpret_cast<const ulonglong2*>(&Ws[buf][k + kk][qp * 8]);
                ulonglong2 w23 =
                    *reinterpret_cast<const ulonglong2*>(&Ws[buf][k + kk][qp * 8 + 4]);
                #pragma unroll
                for (int i = 0; i < 4; ++i) {
                    unsigned long long a2 = pack_dup(kk ? a01[i].y : a01[i].x);
                    fma2(acc[i][0], a2, w01.x);
                    fma2(acc[i][1], a2, w01.y);
                    fma2(acc[i][2], a2, w23.x);
                    fma2(acc[i][3], a2, w23.y);
                }
            }
        }
        __syncthreads();  // compute(c) done everywhere before buf is restaged
    }

    #pragma unroll
    for (int i = 0; i < 4; ++i) {
        int r = row0 + rg * 4 + i;
        if (r < N) {
            ulonglong2 u0, u1;
            u0.x = acc[i][0]; u0.y = acc[i][1];
            u1.x = acc[i][2]; u1.y = acc[i][3];
            *reinterpret_cast<ulonglong2*>(&C[(size_t)r * 96 + qp * 8]) = u0;
            *reinterpret_cast<ulonglong2*>(&C[(size_t)r * 96 + qp * 8 + 4]) = u1;
        }
    }
}

// ---------------- attention scores: es = h@a_s, ed = h@a_d ----------------
__global__ void k_scores(const float* __restrict__ h, const float* __restrict__ as_,
                         const float* __restrict__ ad_, int N) {
    int gw = (blockIdx.x * blockDim.x + threadIdx.x) >> 5;
    if (gw >= N) return;
    int lane = threadIdx.x & 31;
    const float* hr = h + (size_t)gw * 96;
    float s = 0.f, d = 0.f;
    #pragma unroll
    for (int f = 0; f < 3; ++f) {
        float hv = hr[lane + 32 * f];
        s = fmaf(hv, __ldg(&as_[lane + 32 * f]), s);
        d = fmaf(hv, __ldg(&ad_[lane + 32 * f]), d);
    }
    #pragma unroll
    for (int o = 16; o; o >>= 1) {
        s += __shfl_xor_sync(0xffffffffu, s, o);
        d += __shfl_xor_sync(0xffffffffu, d, o);
    }
    if (lane == 0) { g_es[gw] = s; g_ed[gw] = d; }
}

// ---------------- warp-per-node softmax aggregation ----------------
// No max pass (softmax shift-invariance; |e| ~ 15 << fp32 overflow).
// Edge-paired gather with two accumulator sets to halve the FMA dep chain.
__global__ void k_agg(const float* __restrict__ h, const float* __restrict__ bias,
                      float* __restrict__ outp, int N) {
    int gw = (blockIdx.x * blockDim.x + threadIdx.x) >> 5;
    if (gw >= N) return;
    int lane = threadIdx.x & 31;
    int beg = g_rowptr[gw], end = g_rowptr[gw + 1];
    float edn = g_ed[gw];

    const float4* h4 = reinterpret_cast<const float4*>(h);
    float psum = 0.f;
    float4 accA = make_float4(0.f, 0.f, 0.f, 0.f);
    float4 accB = make_float4(0.f, 0.f, 0.f, 0.f);

    for (int j0 = beg; j0 < end; j0 += 32) {
        int j = j0 + lane;
        int s = 0;
        float p = 0.f;
        if (j < end) {
            s = __ldg(&g_csr[j]);
            float e = __ldg(&g_es[s]) + edn;
            e = (e > 0.f) ? e : 0.2f * e;
            p = __expf(e);
        }
        psum += p;
        int cnt = min(32, end - j0);
        int k = 0;
        #pragma unroll 4
        for (; k + 1 < cnt; k += 2) {
            float pk0 = __shfl_sync(0xffffffffu, p, k);
            float pk1 = __shfl_sync(0xffffffffu, p, k + 1);
            int sk0 = __shfl_sync(0xffffffffu, s, k);
            int sk1 = __shfl_sync(0xffffffffu, s, k + 1);
            if (lane < 24) {
                float4 h0 = __ldg(h4 + (size_t)sk0 * 24 + lane);
                float4 h1 = __ldg(h4 + (size_t)sk1 * 24 + lane);
                accA.x = fmaf(pk0, h0.x, accA.x);
                accA.y = fmaf(pk0, h0.y, accA.y);
                accA.z = fmaf(pk0, h0.z, accA.z);
                accA.w = fmaf(pk0, h0.w, accA.w);
                accB.x = fmaf(pk1, h1.x, accB.x);
                accB.y = fmaf(pk1, h1.y, accB.y);
                accB.z = fmaf(pk1, h1.z, accB.z);
                accB.w = fmaf(pk1, h1.w, accB.w);
            }
        }
        if (k < cnt) {
            float pk0 = __shfl_sync(0xffffffffu, p, k);
            int sk0 = __shfl_sync(0xffffffffu, s, k);
            if (lane < 24) {
                float4 h0 = __ldg(h4 + (size_t)sk0 * 24 + lane);
                accA.x = fmaf(pk0, h0.x, accA.x);
                accA.y = fmaf(pk0, h0.y, accA.y);
                accA.z = fmaf(pk0, h0.z, accA.z);
                accA.w = fmaf(pk0, h0.w, accA.w);
            }
        }
    }
    #pragma unroll
    for (int o = 16; o; o >>= 1) psum += __shfl_xor_sync(0xffffffffu, psum, o);

    float degf = (float)(end - beg);
    float scale = (1.f / fmaxf(psum, 1e-16f)) * (1.f / fmaxf(degf, 1.f));
    if (lane < 24) {
        float4 bv = __ldg(reinterpret_cast<const float4*>(bias) + lane);
        float4 r;
        r.x = fmaf(accA.x + accB.x, scale, bv.x);
        r.y = fmaf(accA.y + accB.y, scale, bv.y);
        r.z = fmaf(accA.z + accB.z, scale, bv.z);
        r.w = fmaf(accA.w + accB.w, scale, bv.w);
        reinterpret_cast<float4*>(outp)[(size_t)gw * 24 + lane] = r;
    }
}

// ---------------- reshape(3,N,-1).sum(0) == sum of three contiguous thirds ----------------
template <bool RELU>
__global__ void k_thirds(const float* __restrict__ f, float* __restrict__ o, int n4) {
    int i = blockIdx.x * blockDim.x + threadIdx.x;
    if (i >= n4) return;
    const float4* f4 = reinterpret_cast<const float4*>(f);
    float4 a = f4[i], b = f4[i + n4], c = f4[i + 2 * n4];
    float4 r;
    r.x = a.x + b.x + c.x;
    r.y = a.y + b.y + c.y;
    r.z = a.z + b.z + c.z;
    r.w = a.w + b.w + c.w;
    if (RELU) {
        r.x = fmaxf(r.x, 0.f); r.y = fmaxf(r.y, 0.f);
        r.z = fmaxf(r.z, 0.f); r.w = fmaxf(r.w, 0.f);
    }
    reinterpret_cast<float4*>(o)[i] = r;
}

// ---------------- fused lin1 -> relu -> lin2 -> sigmoid ----------------
__global__ void k_final(const float* __restrict__ t, const float* __restrict__ Wl1,
                        const float* __restrict__ bl1, const float* __restrict__ Wl2,
                        const float* __restrict__ bl2, float* __restrict__ out, int N) {
    __shared__ float w1s[32 * 96];
    __shared__ float w2s[96 * 32];
    __shared__ float b1s[96];
    __shared__ float b2s[32];
    __shared__ float zs[8][96];
    for (int i = threadIdx.x; i < 3072; i += blockDim.x) {
        w1s[i] = Wl1[i];
        w2s[i] = Wl2[i];
    }
    if (threadIdx.x < 96) b1s[threadIdx.x] = bl1[threadIdx.x];
    if (threadIdx.x < 32) b2s[threadIdx.x] = bl2[threadIdx.x];
    __syncthreads();

    int lane = threadIdx.x & 31;
    int wib = threadIdx.x >> 5;
    int gw = blockIdx.x * 8 + wib;
    int stride = gridDim.x * 8;
    float* zr = zs[wib];

    for (int n = gw; n < N; n += stride) {
        float tv = t[(size_t)n * 32 + lane];
        float z0 = b1s[lane], z1 = b1s[lane + 32], z2 = b1s[lane + 64];
        #pragma unroll
        for (int j = 0; j < 32; ++j) {
            float tj = __shfl_sync(0xffffffffu, tv, j);
            z0 = fmaf(tj, w1s[j * 96 + lane], z0);
            z1 = fmaf(tj, w1s[j * 96 + lane + 32], z1);
            z2 = fmaf(tj, w1s[j * 96 + lane + 64], z2);
        }
        zr[lane] = fmaxf(z0, 0.f);
        zr[lane + 32] = fmaxf(z1, 0.f);
        zr[lane + 64] = fmaxf(z2, 0.f);
        __syncwarp();
        float y = b2s[lane];
        #pragma unroll 8
        for (int c = 0; c < 96; ++c) y = fmaf(zr[c], w2s[c * 32 + lane], y);
        out[(size_t)n * 32 + lane] = 1.f / (1.f + __expf(-y));
        __syncwarp();
    }
}

// ---------------- launch ----------------
extern "C" void kernel_launch(void* const* d_in, const int* in_sizes, int n_in,
                              void* d_out, int out_size) {
    const float* x   = (const float*)d_in[0];
    const void*  ei  = d_in[1];
    const float* W1  = (const float*)d_in[2];
    const float* as1 = (const float*)d_in[3];
    const float* ad1 = (const float*)d_in[4];
    const float* b1  = (const float*)d_in[5];
    const float* W2  = (const float*)d_in[6];
    const float* as2 = (const float*)d_in[7];
    const float* ad2 = (const float*)d_in[8];
    const float* b2  = (const float*)d_in[9];
    const float* Wl1 = (const float*)d_in[12];
    const float* bl1 = (const float*)d_in[13];
    const float* Wl2 = (const float*)d_in[14];
    const float* bl2 = (const float*)d_in[15];
    float* out = (float*)d_out;

    int N = in_sizes[0] / 128;
    int E = in_sizes[1] / 2;

    float *p_h, *p_out, *p_small;
    cudaGetSymbolAddress((void**)&p_h, g_h);
    cudaGetSymbolAddress((void**)&p_out, g_out);
    cudaGetSymbolAddress((void**)&p_small, g_small);

    int warpsBlocks = (N * 32 + 255) / 256;
    int G = (N + 1023) / 1024;

    // --- CSR build, with gemm1 at launch #4 (ncu window) ---
    k_probe<<<1, 32>>>((const int*)ei);                       // 1
    k_init_deg<<<(N + 255) / 256, 256>>>(N);                  // 2
    k_count<<<(E + 255) / 256, 256>>>(ei, E, N);              // 3
    k_gemm96<128><<<(N + 127) / 128, 384>>>(x, W1, p_h, N);   // 4 <- ncu window
    k_scan_blocks<<<G, 1024>>>(N);                            // 5
    k_scan_sums<<<1, 1024>>>(G, N);                           // 6
    k_scan_add<<<(N + 255) / 256, 256>>>(N);                  // 7
    k_fill<<<(E + N + 255) / 256, 256>>>(ei, E, N);           // 8

    // --- layer 1 ---
    k_scores<<<warpsBlocks, 256>>>(p_h, as1, ad1, N);
    k_agg<<<warpsBlocks, 256>>>(p_h, b1, p_out, N);
    k_thirds<true><<<(N * 8 + 255) / 256, 256>>>(p_out, p_small, N * 8);

    // --- layer 2 ---
    k_gemm96<32><<<(N + 127) / 128, 384>>>(p_small, W2, p_h, N);
    k_scores<<<warpsBlocks, 256>>>(p_h, as2, ad2, N);
    k_agg<<<warpsBlocks, 256>>>(p_h, b2, p_out, N);
    k_thirds<false><<<(N * 8 + 255) / 256, 256>>>(p_out, p_small, N * 8);

    // --- fused MLP tail ---
    k_final<<<1184, 256>>>(p_small, Wl1, bl1, Wl2, bl2, out, N);
}

// round 12
// speedup vs baseline: 1.0457x; 1.0457x over previous
#include <cuda_runtime.h>
#include <cstdint>
#include <cstddef>

#define NN 100000
#define EE 1600000
#define TT (EE + NN)

// ---------------- scratch (static device globals; no allocation) ----------------
__device__ float g_h[(size_t)NN * 96];      // h (layer1), then h (layer2)
__device__ float g_small[(size_t)NN * 32];  // fused agg+thirds output / gemm2 input / t
__device__ float g_es[NN];
__device__ float g_ed[NN];
__device__ int   g_deg[NN];
__device__ int   g_rowptr[NN + 1];
__device__ int   g_cursor[NN];
__device__ int   g_csr[TT];
__device__ int   g_bsum[1024];
__device__ int   g_is64;

// ---------------- f32x2 / cp.async helpers ----------------
__device__ __forceinline__ unsigned long long pack_dup(float a) {
    unsigned long long r;
    unsigned ai = __float_as_uint(a);
    asm("mov.b64 %0, {%1, %1};" : "=l"(r) : "r"(ai));
    return r;
}
__device__ __forceinline__ void fma2(unsigned long long& d, unsigned long long a,
                                     unsigned long long b) {
    asm("fma.rn.f32x2 %0, %1, %2, %0;" : "+l"(d) : "l"(a), "l"(b));
}
__device__ __forceinline__ void cp16(void* smem_dst, const void* gsrc, int valid_bytes) {
    unsigned sm = (unsigned)__cvta_generic_to_shared(smem_dst);
    asm volatile("cp.async.cg.shared.global [%0], [%1], 16, %2;"
                 :: "r"(sm), "l"(gsrc), "r"(valid_bytes));
}
__device__ __forceinline__ void cp_commit() {
    asm volatile("cp.async.commit_group;" ::: "memory");
}
__device__ __forceinline__ void cp_wait1() {
    asm volatile("cp.async.wait_group 1;" ::: "memory");
}
__device__ __forceinline__ void cp_wait0() {
    asm volatile("cp.async.wait_group 0;" ::: "memory");
}

// ---------------- edge-index dtype probe ----------------
__global__ void k_probe(const int* __restrict__ ei32) {
    if (threadIdx.x == 0 && blockIdx.x == 0) {
        int acc = 0;
        #pragma unroll 8
        for (int i = 1; i < 512; i += 2) acc |= ei32[i];
        g_is64 = (acc == 0) ? 1 : 0;
    }
}

__device__ __forceinline__ int load_idx(const void* ei, size_t i, int is64, int N) {
    int v = is64 ? (int)((const long long*)ei)[i] : ((const int*)ei)[i];
    v = v < 0 ? 0 : v;
    return v >= N ? N - 1 : v;
}

// ---------------- CSR construction ----------------
__global__ void k_init_deg(int N) {
    int i = blockIdx.x * blockDim.x + threadIdx.x;
    if (i < N) g_deg[i] = 1;  // self-loop
}

__global__ void k_count(const void* __restrict__ ei, int E, int N) {
    int i = blockIdx.x * blockDim.x + threadIdx.x;
    if (i < E) {
        int d = load_idx(ei, (size_t)E + i, g_is64, N);
        atomicAdd(&g_deg[d], 1);
    }
}

__global__ void k_scan_blocks(int N) {
    __shared__ int ws[32];
    int i = blockIdx.x * 1024 + threadIdx.x;
    int v = (i < N) ? g_deg[i] : 0;
    int x = v;
    int lane = threadIdx.x & 31, wid = threadIdx.x >> 5;
    #pragma unroll
    for (int o = 1; o < 32; o <<= 1) {
        int y = __shfl_up_sync(0xffffffffu, x, o);
        if (lane >= o) x += y;
    }
    if (lane == 31) ws[wid] = x;
    __syncthreads();
    if (wid == 0) {
        int w = ws[lane];
        #pragma unroll
        for (int o = 1; o < 32; o <<= 1) {
            int y = __shfl_up_sync(0xffffffffu, w, o);
            if (lane >= o) w += y;
        }
        ws[lane] = w;
    }
    __syncthreads();
    int excl = x - v + (wid ? ws[wid - 1] : 0);
    if (i < N) g_rowptr[i] = excl;
    if (threadIdx.x == 1023) g_bsum[blockIdx.x] = ws[31];
}

__global__ void k_scan_sums(int G, int N) {
    __shared__ int ws[32];
    int tid = threadIdx.x;
    int v = (tid < G) ? g_bsum[tid] : 0;
    int x = v;
    int lane = tid & 31, wid = tid >> 5;
    #pragma unroll
    for (int o = 1; o < 32; o <<= 1) {
        int y = __shfl_up_sync(0xffffffffu, x, o);
        if (lane >= o) x += y;
    }
    if (lane == 31) ws[wid] = x;
    __syncthreads();
    if (wid == 0) {
        int w = ws[lane];
        #pragma unroll
        for (int o = 1; o < 32; o <<= 1) {
            int y = __shfl_up_sync(0xffffffffu, w, o);
            if (lane >= o) w += y;
        }
        ws[lane] = w;
    }
    __syncthreads();
    int excl = x - v + (wid ? ws[wid - 1] : 0);
    if (tid < G) g_bsum[tid] = excl;
    if (tid == 1023) g_rowptr[N] = ws[31];
}

__global__ void k_scan_add(int N) {
    int i = blockIdx.x * blockDim.x + threadIdx.x;
    if (i < N) {
        int v = g_rowptr[i] + g_bsum[i >> 10];
        g_rowptr[i] = v;
        g_cursor[i] = v;
    }
}

__global__ void k_fill(const void* __restrict__ ei, int E, int N) {
    int i = blockIdx.x * blockDim.x + threadIdx.x;
    int tot = E + N;
    if (i >= tot) return;
    int s, d;
    if (i < E) {
        int is64 = g_is64;
        s = load_idx(ei, i, is64, N);
        d = load_idx(ei, (size_t)E + i, is64, N);
    } else {
        s = i - E;
        d = s;
    }
    int pos = atomicAdd(&g_cursor[d], 1);
    if (pos < TT) g_csr[pos] = s;
}

// ---------------- GEMM: C[N,96] = A[N,K] @ W[K,96], f32x2, 3-buffer cp.async ----------
// block: 128 rows x 96 cols, 384 threads, thread tile 4 rows x 8 cols.
// KC=16, 3 smem buffers (48.0 KB static), stage distance 2, ONE sync per chunk.
// Ring safety: stage(c+2) writes buf (c-1)%3, which the sync just released.
template <int K>
__global__ __launch_bounds__(384, 2)
void k_gemm96(const float* __restrict__ A, const float* __restrict__ W,
              float* __restrict__ C, int N) {
    constexpr int KC = 16;
    constexpr int NCH = K / KC;
    __shared__ float As[3][128][KC + 4];   // 3*10240 B
    __shared__ float Ws[3][KC][96];        // 3*6144 B  (total = 49152 B)
    int tid = threadIdx.x;
    int row0 = blockIdx.x * 128;
    int qp = tid % 12;  // cols qp*8 .. qp*8+7
    int rg = tid / 12;  // rows rg*4 .. rg*4+3

    auto stage = [&](int c, int buf) {
        for (int i = tid; i < KC * 24; i += 384) {
            int k = i / 24, q = i % 24;
            cp16(&Ws[buf][k][q * 4], W + (size_t)(c * KC + k) * 96 + q * 4, 16);
        }
        for (int i = tid; i < 128 * (KC / 4); i += 384) {
            int r = i / (KC / 4), kq = i % (KC / 4);
            bool ok = (row0 + r) < N;
            const float* src = A + (ok ? ((size_t)(row0 + r) * K + c * KC + kq * 4) : 0);
            cp16(&As[buf][r][kq * 4], src, ok ? 16 : 0);
        }
    };

    unsigned long long acc[4][4];
    #pragma unroll
    for (int i = 0; i < 4; ++i)
        #pragma unroll
        for (int j = 0; j < 4; ++j) acc[i][j] = 0ull;

    stage(0, 0);
    cp_commit();
    if (NCH > 1) { stage(1, 1); cp_commit(); }

    #pragma unroll
    for (int c = 0; c < NCH; ++c) {
        if (c + 1 < NCH) cp_wait1(); else cp_wait0();  // chunk c landed
        __syncthreads();                               // everyone done with c-1; c visible
        if (c + 2 < NCH) { stage(c + 2, (c + 2) % 3); cp_commit(); }

        int buf = c % 3;
        #pragma unroll
        for (int k = 0; k < KC; k += 2) {
            float2 a01[4];
            #pragma unroll
            for (int i = 0; i < 4; ++i)
                a01[i] = *reinterpret_cast<const float2*>(&As[buf][rg * 4 + i][k]);
            #pragma unroll
            for (int kk = 0; kk < 2; ++kk) {
                ulonglong2 w01 =
                    *reinterpret_cast<const ulonglong2*>(&Ws[buf][k + kk][qp * 8]);
                ulonglong2 w23 =
                    *reinterpret_cast<const ulonglong2*>(&Ws[buf][k + kk][qp * 8 + 4]);
                #pragma unroll
                for (int i = 0; i < 4; ++i) {
                    unsigned long long a2 = pack_dup(kk ? a01[i].y : a01[i].x);
                    fma2(acc[i][0], a2, w01.x);
                    fma2(acc[i][1], a2, w01.y);
                    fma2(acc[i][2], a2, w23.x);
                    fma2(acc[i][3], a2, w23.y);
                }
            }
        }
    }

    #pragma unroll
    for (int i = 0; i < 4; ++i) {
        int r = row0 + rg * 4 + i;
        if (r < N) {
            ulonglong2 u0, u1;
            u0.x = acc[i][0]; u0.y = acc[i][1];
            u1.x = acc[i][2]; u1.y = acc[i][3];
            *reinterpret_cast<ulonglong2*>(&C[(size_t)r * 96 + qp * 8]) = u0;
            *reinterpret_cast<ulonglong2*>(&C[(size_t)r * 96 + qp * 8 + 4]) = u1;
        }
    }
}

// ---------------- attention scores: es = h@a_s, ed = h@a_d ----------------
__global__ void k_scores(const float* __restrict__ h, const float* __restrict__ as_,
                         const float* __restrict__ ad_, int N) {
    int gw = (blockIdx.x * blockDim.x + threadIdx.x) >> 5;
    if (gw >= N) return;
    int lane = threadIdx.x & 31;
    const float* hr = h + (size_t)gw * 96;
    float s = 0.f, d = 0.f;
    #pragma unroll
    for (int f = 0; f < 3; ++f) {
        float hv = hr[lane + 32 * f];
        s = fmaf(hv, __ldg(&as_[lane + 32 * f]), s);
        d = fmaf(hv, __ldg(&ad_[lane + 32 * f]), d);
    }
    #pragma unroll
    for (int o = 16; o; o >>= 1) {
        s += __shfl_xor_sync(0xffffffffu, s, o);
        d += __shfl_xor_sync(0xffffffffu, d, o);
    }
    if (lane == 0) { g_es[gw] = s; g_ed[gw] = d; }
}

// ---------------- warp-per-node softmax aggregation, FUSED with thirds-sum ----------
// No max pass (softmax shift-invariance; |e| ~ 15 << fp32 overflow).
// Epilogue: out96 cols (c, c+32, c+64) live at lanes (l, l+8, l+16) same component,
// so reshape(3,N,32).sum(0) is two shuffles; lanes 0..7 write 32 floats to `small`.
template <bool RELU>
__global__ void k_agg(const float* __restrict__ h, const float* __restrict__ bias,
                      float* __restrict__ small, int N) {
    int gw = (blockIdx.x * blockDim.x + threadIdx.x) >> 5;
    if (gw >= N) return;
    int lane = threadIdx.x & 31;
    int beg = g_rowptr[gw], end = g_rowptr[gw + 1];
    float edn = g_ed[gw];

    const float4* h4 = reinterpret_cast<const float4*>(h);
    float psum = 0.f;
    float4 accA = make_float4(0.f, 0.f, 0.f, 0.f);
    float4 accB = make_float4(0.f, 0.f, 0.f, 0.f);

    for (int j0 = beg; j0 < end; j0 += 32) {
        int j = j0 + lane;
        int s = 0;
        float p = 0.f;
        if (j < end) {
            s = __ldg(&g_csr[j]);
            float e = __ldg(&g_es[s]) + edn;
            e = (e > 0.f) ? e : 0.2f * e;
            p = __expf(e);
        }
        psum += p;
        int cnt = min(32, end - j0);
        int k = 0;
        #pragma unroll 4
        for (; k + 1 < cnt; k += 2) {
            float pk0 = __shfl_sync(0xffffffffu, p, k);
            float pk1 = __shfl_sync(0xffffffffu, p, k + 1);
            int sk0 = __shfl_sync(0xffffffffu, s, k);
            int sk1 = __shfl_sync(0xffffffffu, s, k + 1);
            if (lane < 24) {
                float4 h0 = __ldg(h4 + (size_t)sk0 * 24 + lane);
                float4 h1 = __ldg(h4 + (size_t)sk1 * 24 + lane);
                accA.x = fmaf(pk0, h0.x, accA.x);
                accA.y = fmaf(pk0, h0.y, accA.y);
                accA.z = fmaf(pk0, h0.z, accA.z);
                accA.w = fmaf(pk0, h0.w, accA.w);
                accB.x = fmaf(pk1, h1.x, accB.x);
                accB.y = fmaf(pk1, h1.y, accB.y);
                accB.z = fmaf(pk1, h1.z, accB.z);
                accB.w = fmaf(pk1, h1.w, accB.w);
            }
        }
        if (k < cnt) {
            float pk0 = __shfl_sync(0xffffffffu, p, k);
            int sk0 = __shfl_sync(0xffffffffu, s, k);
            if (lane < 24) {
                float4 h0 = __ldg(h4 + (size_t)sk0 * 24 + lane);
                accA.x = fmaf(pk0, h0.x, accA.x);
                accA.y = fmaf(pk0, h0.y, accA.y);
                accA.z = fmaf(pk0, h0.z, accA.z);
                accA.w = fmaf(pk0, h0.w, accA.w);
            }
        }
    }
    #pragma unroll
    for (int o = 16; o; o >>= 1) psum += __shfl_xor_sync(0xffffffffu, psum, o);

    float degf = (float)(end - beg);
    float scale = (1.f / fmaxf(psum, 1e-16f)) * (1.f / fmaxf(degf, 1.f));

    // biased 96-col result at all lanes (lanes >=24 hold junk, never sourced)
    float4 bv = __ldg(reinterpret_cast<const float4*>(bias) + (lane < 24 ? lane : 23));
    float4 r;
    r.x = fmaf(accA.x + accB.x, scale, bv.x);
    r.y = fmaf(accA.y + accB.y, scale, bv.y);
    r.z = fmaf(accA.z + accB.z, scale, bv.z);
    r.w = fmaf(accA.w + accB.w, scale, bv.w);

    // thirds-sum via shuffles: s(l) = r(l) + r(l+8) + r(l+16), l < 8
    float4 r8, r16;
    r8.x  = __shfl_sync(0xffffffffu, r.x, lane + 8);
    r8.y  = __shfl_sync(0xffffffffu, r.y, lane + 8);
    r8.z  = __shfl_sync(0xffffffffu, r.z, lane + 8);
    r8.w  = __shfl_sync(0xffffffffu, r.w, lane + 8);
    r16.x = __shfl_sync(0xffffffffu, r.x, lane + 16);
    r16.y = __shfl_sync(0xffffffffu, r.y, lane + 16);
    r16.z = __shfl_sync(0xffffffffu, r.z, lane + 16);
    r16.w = __shfl_sync(0xffffffffu, r.w, lane + 16);
    if (lane < 8) {
        float4 sres;
        sres.x = r.x + r8.x + r16.x;
        sres.y = r.y + r8.y + r16.y;
        sres.z = r.z + r8.z + r16.z;
        sres.w = r.w + r8.w + r16.w;
        if (RELU) {
            sres.x = fmaxf(sres.x, 0.f);
            sres.y = fmaxf(sres.y, 0.f);
            sres.z = fmaxf(sres.z, 0.f);
            sres.w = fmaxf(sres.w, 0.f);
        }
        reinterpret_cast<float4*>(small)[(size_t)gw * 8 + lane] = sres;
    }
}

// ---------------- fused lin1 -> relu -> lin2 -> sigmoid ----------------
__global__ void k_final(const float* __restrict__ t, const float* __restrict__ Wl1,
                        const float* __restrict__ bl1, const float* __restrict__ Wl2,
                        const float* __restrict__ bl2, float* __restrict__ out, int N) {
    __shared__ float w1s[32 * 96];
    __shared__ float w2s[96 * 32];
    __shared__ float b1s[96];
    __shared__ float b2s[32];
    __shared__ float zs[8][96];
    for (int i = threadIdx.x; i < 3072; i += blockDim.x) {
        w1s[i] = Wl1[i];
        w2s[i] = Wl2[i];
    }
    if (threadIdx.x < 96) b1s[threadIdx.x] = bl1[threadIdx.x];
    if (threadIdx.x < 32) b2s[threadIdx.x] = bl2[threadIdx.x];
    __syncthreads();

    int lane = threadIdx.x & 31;
    int wib = threadIdx.x >> 5;
    int gw = blockIdx.x * 8 + wib;
    int stride = gridDim.x * 8;
    float* zr = zs[wib];

    for (int n = gw; n < N; n += stride) {
        float tv = t[(size_t)n * 32 + lane];
        float z0 = b1s[lane], z1 = b1s[lane + 32], z2 = b1s[lane + 64];
        #pragma unroll
        for (int j = 0; j < 32; ++j) {
            float tj = __shfl_sync(0xffffffffu, tv, j);
            z0 = fmaf(tj, w1s[j * 96 + lane], z0);
            z1 = fmaf(tj, w1s[j * 96 + lane + 32], z1);
            z2 = fmaf(tj, w1s[j * 96 + lane + 64], z2);
        }
        zr[lane] = fmaxf(z0, 0.f);
        zr[lane + 32] = fmaxf(z1, 0.f);
        zr[lane + 64] = fmaxf(z2, 0.f);
        __syncwarp();
        float y = b2s[lane];
        #pragma unroll 8
        for (int c = 0; c < 96; ++c) y = fmaf(zr[c], w2s[c * 32 + lane], y);
        out[(size_t)n * 32 + lane] = 1.f / (1.f + __expf(-y));
        __syncwarp();
    }
}

// ---------------- launch ----------------
extern "C" void kernel_launch(void* const* d_in, const int* in_sizes, int n_in,
                              void* d_out, int out_size) {
    const float* x   = (const float*)d_in[0];
    const void*  ei  = d_in[1];
    const float* W1  = (const float*)d_in[2];
    const float* as1 = (const float*)d_in[3];
    const float* ad1 = (const float*)d_in[4];
    const float* b1  = (const float*)d_in[5];
    const float* W2  = (const float*)d_in[6];
    const float* as2 = (const float*)d_in[7];
    const float* ad2 = (const float*)d_in[8];
    const float* b2  = (const float*)d_in[9];
    const float* Wl1 = (const float*)d_in[12];
    const float* bl1 = (const float*)d_in[13];
    const float* Wl2 = (const float*)d_in[14];
    const float* bl2 = (const float*)d_in[15];
    float* out = (float*)d_out;

    int N = in_sizes[0] / 128;
    int E = in_sizes[1] / 2;

    float *p_h, *p_small;
    cudaGetSymbolAddress((void**)&p_h, g_h);
    cudaGetSymbolAddress((void**)&p_small, g_small);

    int warpsBlocks = (N * 32 + 255) / 256;
    int G = (N + 1023) / 1024;

    // --- CSR build, with gemm1 at launch #4 (ncu window) ---
    k_probe<<<1, 32>>>((const int*)ei);                       // 1
    k_init_deg<<<(N + 255) / 256, 256>>>(N);                  // 2
    k_count<<<(E + 255) / 256, 256>>>(ei, E, N);              // 3
    k_gemm96<128><<<(N + 127) / 128, 384>>>(x, W1, p_h, N);   // 4 <- ncu window
    k_scan_blocks<<<G, 1024>>>(N);                            // 5
    k_scan_sums<<<1, 1024>>>(G, N);                           // 6
    k_scan_add<<<(N + 255) / 256, 256>>>(N);                  // 7
    k_fill<<<(E + N + 255) / 256, 256>>>(ei, E, N);           // 8

    // --- layer 1 (agg writes thirds-summed+relu result straight to g_small) ---
    k_scores<<<warpsBlocks, 256>>>(p_h, as1, ad1, N);
    k_agg<true><<<warpsBlocks, 256>>>(p_h, b1, p_small, N);

    // --- layer 2 ---
    k_gemm96<32><<<(N + 127) / 128, 384>>>(p_small, W2, p_h, N);
    k_scores<<<warpsBlocks, 256>>>(p_h, as2, ad2, N);
    k_agg<false><<<warpsBlocks, 256>>>(p_h, b2, p_small, N);

    // --- fused MLP tail ---
    k_final<<<1184, 256>>>(p_small, Wl1, bl1, Wl2, bl2, out, N);
}